// round 5
// baseline (speedup 1.0000x reference)
#include <cuda_runtime.h>
#include <stdint.h>
#include <cub/block/block_radix_sort.cuh>

#define BN 64
#define GN 4999
#define PN 50
#define PW 157            // ceil(4999/32)
#define SEG 157           // positions per lane
#define GSTRIDE 5024      // 32*157, padded length

__device__ __align__(16) unsigned d_pbits[PN * PW];

// ---------------------------------------------------------------------------
// Kernel 1: pathway bitmask. One 32-gene word per thread, 32 unrolled loads.
// ---------------------------------------------------------------------------
__global__ void pbuild_kernel(const float* __restrict__ pw) {
    const int t = blockIdx.x * blockDim.x + threadIdx.x;
    if (t >= PN * PW) return;
    const int p  = t / PW;
    const int wi = t % PW;
    const float* base = pw + (size_t)p * GN + wi * 32;
    const int cnt = (wi == PW - 1) ? (GN - (PW - 1) * 32) : 32;   // last word: 7
    unsigned bits = 0;
    #pragma unroll
    for (int q = 0; q < 32; q++) {
        if (q < cnt && base[q] > 0.0f) bits |= 1u << q;
    }
    d_pbits[t] = bits;
}

// ---------------------------------------------------------------------------
// Kernel 2 (fused): per-sample stable descending sort + all-pathway enrichment.
// Sort: cub BlockRadixSort pairs (u32 monotone key, u16 gene index), radix-5,
// 7 passes over 32 bits. Blocked load order = gene index order, and radix
// sort is stable => ties break by ascending gene index (matches argsort).
// Then 25 warps x 2 pathways compute the ES statistic from smem.
// ---------------------------------------------------------------------------
#define ST 1024
#define SI 5              // 5120 slots >= 4999

typedef cub::BlockRadixSort<unsigned, ST, SI, unsigned short, 5> SorterT;

__global__ void __launch_bounds__(ST, 1)
fused_kernel(const float* __restrict__ expr, float* __restrict__ out) {
    extern __shared__ char smem[];
    int*   s_order = (int*)smem;                       // GSTRIDE ints   (20096 B)
    float* s_w     = (float*)(s_order + GSTRIDE);      // GSTRIDE floats (20096 B)
    char*  s_rest  = (char*)(s_w + GSTRIDE);           // union: sort temp | pbits+hb

    const int b   = blockIdx.x;
    const int tid = threadIdx.x;
    const float* row = expr + (size_t)b * GN;

    // ---- blocked load: thread t owns genes [t*SI, t*SI+SI) ----
    unsigned       keys[SI];
    unsigned short vals[SI];
    #pragma unroll
    for (int j = 0; j < SI; j++) {
        int pos = tid * SI + j;
        if (pos < GN) {
            unsigned u = __float_as_uint(row[pos]);
            u = (u & 0x80000000u) ? ~u : (u | 0x80000000u);   // ascending map
            keys[j] = ~u;                                      // descending
            vals[j] = (unsigned short)pos;
        } else {
            keys[j] = 0xFFFFFFFFu;                             // pads sort last
            vals[j] = 0;
        }
    }

    {
        typename SorterT::TempStorage& ts =
            *reinterpret_cast<typename SorterT::TempStorage*>(s_rest);
        SorterT(ts).Sort(keys, vals, 0, 32);
    }

    // ---- write sorted order + |x|^0.25 weights into smem ----
    #pragma unroll
    for (int j = 0; j < SI; j++) {
        int pos = tid * SI + j;                  // blocked after sort
        if (pos < GSTRIDE) {
            if (pos < GN) {
                unsigned u = ~keys[j];           // invert descending map
                unsigned absbits = (u & 0x80000000u) ? (u & 0x7FFFFFFFu)
                                                     : ((~u) & 0x7FFFFFFFu);
                s_order[pos] = (int)vals[j];
                s_w[pos]     = sqrtf(sqrtf(__uint_as_float(absbits)));
            } else {
                s_order[pos] = 0;                // pad: forced hit, w = 0
                s_w[pos]     = 0.0f;
            }
        }
    }
    __syncthreads();                             // sort temp now dead

    // ---- load pathway bits over the dead sort temp ----
    unsigned* s_pb = (unsigned*)s_rest;          // PN*PW words (31400 B)
    unsigned* s_hb = s_pb + PN * PW;             // 25*32*5 words (16000 B)
    for (int i = tid; i < PN * PW; i += ST) s_pb[i] = d_pbits[i];
    __syncthreads();

    const int wid  = tid >> 5;
    const int lane = tid & 31;
    if (wid >= 25) return;                       // warps 25-31 done (no syncs below)

    unsigned* hbl = s_hb + (wid * 32 + lane) * 5;   // stride-5: conflict-free
    const int start = lane * SEG;

    #pragma unroll 1
    for (int pp = 0; pp < 2; pp++) {
        const int p = wid * 2 + pp;
        const unsigned* pb = s_pb + p * PW;

        // ---- pass A: probe hits -> bit words; hit-weight sum ----
        float hw = 0.0f;
        int hits = 0;
        #pragma unroll
        for (int wi = 0; wi < 5; wi++) {
            const int cnt = (wi == 4) ? 29 : 32;   // 4*32 + 29 = 157
            unsigned bits = 0;
            #pragma unroll
            for (int q = 0; q < cnt; q++) {
                int i = start + wi * 32 + q;
                int g = s_order[i];
                unsigned hit = (pb[g >> 5] >> (g & 31)) & 1u;
                bits |= hit << q;
                if (hit) hw += s_w[i];
            }
            // pads (i >= GN): lane 31, word 4, q in [4,28] -> forced hits (w=0)
            if (wi == 4 && lane == 31) bits |= 0x1FFFFFF0u;
            hbl[wi] = bits;
            hits += __popc(bits);
        }
        int mc = SEG - hits;

        // warp totals: S (hit weight), size (= total hits - 25 pads)
        float S = hw;
        int   th = hits;
        #pragma unroll
        for (int off = 16; off; off >>= 1) {
            S  += __shfl_xor_sync(0xffffffffu, S, off);
            th += __shfl_xor_sync(0xffffffffu, th, off);
        }
        const int size = th - 25;

        const float inv_denom = 1.0f / fmaxf((float)(GN - size), 1.0f);
        const float invS      = (S > 0.0f) ? (1.0f / S) : 1.0f;

        // exclusive prefix of per-lane net delta -> lane's starting r
        float lane_delta = hw * invS - (float)mc * inv_denom;
        float v = lane_delta;
        #pragma unroll
        for (int off = 1; off < 32; off <<= 1) {
            float t = __shfl_up_sync(0xffffffffu, v, off);
            if (lane >= off) v += t;
        }
        float r = v - lane_delta;                // exclusive prefix

        // ---- pass B: replay bits, track first argmax |r| ----
        float best_abs = -1.0f, best_val = 0.0f;
        int   best_idx = 0x7fffffff;
        #pragma unroll
        for (int wi = 0; wi < 5; wi++) {
            unsigned bits = hbl[wi];
            const int cnt = (wi == 4) ? 29 : 32;
            #pragma unroll
            for (int q = 0; q < cnt; q++) {
                int i = start + wi * 32 + q;
                float wv = s_w[i];
                r = (bits & (1u << q)) ? fmaf(wv, invS, r) : (r - inv_denom);
                float ar = fabsf(r);
                bool better = ar > best_abs;
                best_abs = better ? ar : best_abs;
                best_val = better ? r  : best_val;
                best_idx = better ? i  : best_idx;
            }
        }

        // ---- cross-lane argmax reduce (tie -> smallest index) ----
        #pragma unroll
        for (int off = 16; off; off >>= 1) {
            float oa = __shfl_down_sync(0xffffffffu, best_abs, off);
            float ov = __shfl_down_sync(0xffffffffu, best_val, off);
            int   oi = __shfl_down_sync(0xffffffffu, best_idx, off);
            if (oa > best_abs || (oa == best_abs && oi < best_idx)) {
                best_abs = oa; best_val = ov; best_idx = oi;
            }
        }
        if (lane == 0) out[b * PN + p] = (size > 0) ? best_val : 0.0f;
    }
}

// ---------------------------------------------------------------------------
extern "C" void kernel_launch(void* const* d_in, const int* in_sizes, int n_in,
                              void* d_out, int out_size) {
    const float* expr = (const float*)d_in[0];   // [B, G]
    const float* pw   = (const float*)d_in[1];   // [P, G]
    float* out        = (float*)d_out;           // [B, P]

    const int head    = GSTRIDE * 8;                               // order + w
    const int es_rest = PN * PW * 4 + 25 * 32 * 5 * 4;             // pbits + hb
    const int sort_ts = (int)sizeof(typename SorterT::TempStorage);
    const int rest    = (sort_ts > es_rest) ? sort_ts : es_rest;
    const int fused_smem = head + rest;

    cudaFuncSetAttribute(fused_kernel,
                         cudaFuncAttributeMaxDynamicSharedMemorySize, fused_smem);

    pbuild_kernel<<<(PN * PW + 255) / 256, 256>>>(pw);
    fused_kernel<<<BN, ST, fused_smem>>>(expr, out);
}

// round 7
// speedup vs baseline: 1.1920x; 1.1920x over previous
#include <cuda_runtime.h>
#include <stdint.h>

#define BN 64
#define GN 4999
#define PN 50
#define SEG 157           // positions per lane
#define GSTRIDE 5024      // 32*157
#define NW 157            // position words per pathway
#define NBKT 4096

__device__ __align__(16) unsigned d_gbits[2 * GN];   // gene-major pathway bits

// ---------------------------------------------------------------------------
// Kernel 1: gene-major pathway bitmask. Thread per gene, 50 coalesced loads.
// ---------------------------------------------------------------------------
__global__ void pbuild_kernel(const float* __restrict__ pw) {
    const int g = blockIdx.x * blockDim.x + threadIdx.x;
    if (g >= GN) return;
    unsigned w0 = 0, w1 = 0;
    #pragma unroll
    for (int p = 0; p < 32; p++)
        if (pw[(size_t)p * GN + g] > 0.0f) w0 |= 1u << p;
    #pragma unroll
    for (int p = 32; p < PN; p++)
        if (pw[(size_t)p * GN + g] > 0.0f) w1 |= 1u << (p - 32);
    d_gbits[2 * g]     = w0;
    d_gbits[2 * g + 1] = w1;
}

// ---------------------------------------------------------------------------
// Kernel 2 (fused): bucket sort + positional masks + enrichment. 1 block/sample.
//
// Sort: bucket by clamp((4-x)*512) (monotone with descending x), smem
// histogram + block scan + atomic scatter, then per-bucket insertion sort on
// the full unique key (dsc<<13 | idx) -> deterministic stable-equivalent order.
// Masks: ballot-transpose gene-major bits into position-indexed words.
// ES: 25 warps x 2 pathways, lane owns 157 consecutive positions.
// ---------------------------------------------------------------------------
#define ST 1024

// smem layout (bytes) — every region 16-byte aligned
#define OFF_KEYS   0                         // u64[5024]  -> later u32 gbits[2*GN]
#define OFF_ORDER  40192                     // int[5024]
#define OFF_W      60288                     // float[5024]
#define OFF_MASK   80384                     // u32[50*157] = 31400 B
#define OFF_HIST   111792                    // u32[4096] (padded to 16B align)
#define OFF_WAUX   128176                    // u32[32]
#define SMEM_TOTAL 128304

__global__ void __launch_bounds__(ST, 1)
fused_kernel(const float* __restrict__ expr, float* __restrict__ out) {
    extern __shared__ char smem[];
    unsigned long long* s_keys = (unsigned long long*)(smem + OFF_KEYS);
    int*      s_order = (int*)(smem + OFF_ORDER);
    float*    s_w     = (float*)(smem + OFF_W);
    unsigned* s_mask  = (unsigned*)(smem + OFF_MASK);
    unsigned* s_hist  = (unsigned*)(smem + OFF_HIST);
    unsigned* s_waux  = (unsigned*)(smem + OFF_WAUX);
    unsigned* s_gbits = (unsigned*)(smem + OFF_KEYS);   // alias, after sort

    const int b    = blockIdx.x;
    const int tid  = threadIdx.x;
    const int wid  = tid >> 5;
    const int lane = tid & 31;
    const float* row = expr + (size_t)b * GN;

    // ---- phase 1: zero histogram ----
    ((uint4*)s_hist)[tid] = make_uint4(0, 0, 0, 0);
    __syncthreads();

    // ---- phase 2: load, build keys + buckets, histogram ----
    unsigned long long key[5];
    int bkt[5];
    #pragma unroll
    for (int j = 0; j < 5; j++) {
        int i = j * ST + tid;                     // striped, coalesced
        if (i < GN) {
            float x = row[i];
            unsigned u = __float_as_uint(x);
            u = (u & 0x80000000u) ? ~u : (u | 0x80000000u);    // ascending map
            unsigned dsc = ~u;                                  // descending
            key[j] = ((unsigned long long)dsc << 13) | (unsigned)i;
            int bb = (int)((4.0f - x) * 512.0f);
            bb = bb < 0 ? 0 : (bb > NBKT - 1 ? NBKT - 1 : bb);
            bkt[j] = bb;
            atomicAdd(&s_hist[bb], 1u);
        } else {
            bkt[j] = -1;
        }
    }
    __syncthreads();

    // ---- phase 3: exclusive scan over 4096 bins (4 per thread) ----
    {
        uint4 h = ((uint4*)s_hist)[tid];
        unsigned lsum = h.x + h.y + h.z + h.w;
        unsigned v = lsum;
        #pragma unroll
        for (int off = 1; off < 32; off <<= 1) {
            unsigned n = __shfl_up_sync(0xffffffffu, v, off);
            if (lane >= off) v += n;
        }
        if (lane == 31) s_waux[wid] = v;
        __syncthreads();
        if (wid == 0) {
            unsigned wv = s_waux[lane];
            unsigned vv = wv;
            #pragma unroll
            for (int off = 1; off < 32; off <<= 1) {
                unsigned n = __shfl_up_sync(0xffffffffu, vv, off);
                if (lane >= off) vv += n;
            }
            s_waux[lane] = vv - wv;              // exclusive warp bases
        }
        __syncthreads();
        unsigned base = s_waux[wid] + (v - lsum);
        uint4 o;
        o.x = base;
        o.y = o.x + h.x;
        o.z = o.y + h.y;
        o.w = o.z + h.z;
        __syncthreads();                          // all reads of h done
        ((uint4*)s_hist)[tid] = o;                // hist -> exclusive offsets
    }
    __syncthreads();

    // ---- phase 4: scatter keys into bucket regions ----
    #pragma unroll
    for (int j = 0; j < 5; j++) {
        if (bkt[j] >= 0) {
            unsigned pos = atomicAdd(&s_hist[bkt[j]], 1u);
            s_keys[pos] = key[j];
        }
    }
    __syncthreads();
    // s_hist[bb] now = end offset of bucket bb

    // ---- phase 5: insertion sort within each bucket (full unique key) ----
    {
        #pragma unroll
        for (int q = 0; q < 4; q++) {
            int bb = tid * 4 + q;
            int st = (bb == 0) ? 0 : (int)s_hist[bb - 1];
            int en = (int)s_hist[bb];
            for (int i = st + 1; i < en; i++) {
                unsigned long long k = s_keys[i];
                int j = i - 1;
                while (j >= st && s_keys[j] > k) {
                    s_keys[j + 1] = s_keys[j];
                    j--;
                }
                s_keys[j + 1] = k;
            }
        }
    }
    __syncthreads();

    // ---- phase 6: materialize order + |x|^0.25 weights ----
    #pragma unroll
    for (int j = 0; j < 5; j++) {
        int pos = j * ST + tid;
        if (pos < GN) {
            unsigned long long k = s_keys[pos];
            int idx = (int)(k & 0x1FFFull);
            unsigned u = ~((unsigned)(k >> 13));
            unsigned absbits = (u & 0x80000000u) ? (u & 0x7FFFFFFFu)
                                                 : ((~u) & 0x7FFFFFFFu);
            s_order[pos] = idx;
            s_w[pos]     = sqrtf(sqrtf(__uint_as_float(absbits)));
        } else if (pos < GSTRIDE) {
            s_order[pos] = 0;                     // pad: forced hit, w = 0
            s_w[pos]     = 0.0f;
        }
    }
    __syncthreads();                              // s_keys dead

    // ---- phase 7: gene-major bits -> smem (overlays s_keys) ----
    for (int i = tid; i < 2 * GN; i += ST) s_gbits[i] = d_gbits[i];
    __syncthreads();

    // ---- phase 8: transpose to position-indexed masks via ballot ----
    for (int wi = wid; wi < NW; wi += 32) {
        int pos = wi * 32 + lane;
        int g = s_order[pos];
        unsigned hv0 = s_gbits[2 * g];
        unsigned hv1 = s_gbits[2 * g + 1];
        unsigned m0 = 0, m1 = 0;
        #pragma unroll
        for (int p = 0; p < 32; p++) {
            unsigned bl = __ballot_sync(0xffffffffu, (hv0 >> p) & 1u);
            if (lane == p) m0 = bl;
        }
        #pragma unroll
        for (int p = 0; p < 18; p++) {
            unsigned bl = __ballot_sync(0xffffffffu, (hv1 >> p) & 1u);
            if (lane == p) m1 = bl;
        }
        s_mask[lane * NW + wi] = m0;              // pathway = lane
        if (lane < 18) s_mask[(32 + lane) * NW + wi] = m1;
    }
    __syncthreads();
    // pads (positions 4999..5023 = word 156 bits 7..31): force hits (w=0)
    if (tid < PN) s_mask[tid * NW + 156] |= 0xFFFFFF80u;
    __syncthreads();

    // ---- phase 9: enrichment. warp w -> pathways 2w, 2w+1 ----
    if (wid >= 25) return;
    const int p0 = 2 * wid;
    const unsigned* mp0 = s_mask + p0 * NW;
    const unsigned* mp1 = mp0 + NW;
    const int start = lane * SEG;

    // pass A: per-lane hit-weight sums + hit counts
    float hw0 = 0.0f, hw1 = 0.0f;
    int   c0 = 0, c1 = 0;
    {
        unsigned m0 = 0, m1 = 0;
        for (int k = 0; k < SEG; k++) {
            int i  = start + k;
            int sh = i & 31;
            if (k == 0 || sh == 0) { m0 = mp0[i >> 5]; m1 = mp1[i >> 5]; }
            float wv = s_w[i];
            unsigned b0 = (m0 >> sh) & 1u;
            unsigned b1 = (m1 >> sh) & 1u;
            hw0 += b0 ? wv : 0.0f;
            hw1 += b1 ? wv : 0.0f;
            c0 += b0; c1 += b1;
        }
    }

    // warp totals
    float S0 = hw0, S1 = hw1;
    int   t0 = c0,  t1 = c1;
    #pragma unroll
    for (int off = 16; off; off >>= 1) {
        S0 += __shfl_xor_sync(0xffffffffu, S0, off);
        S1 += __shfl_xor_sync(0xffffffffu, S1, off);
        t0 += __shfl_xor_sync(0xffffffffu, t0, off);
        t1 += __shfl_xor_sync(0xffffffffu, t1, off);
    }
    const int size0 = t0 - 25, size1 = t1 - 25;   // 25 pads, all in lane 31
    const float invd0 = 1.0f / fmaxf((float)(GN - size0), 1.0f);
    const float invd1 = 1.0f / fmaxf((float)(GN - size1), 1.0f);
    const float invS0 = (S0 > 0.0f) ? (1.0f / S0) : 1.0f;
    const float invS1 = (S1 > 0.0f) ? (1.0f / S1) : 1.0f;

    // exclusive prefix of per-lane net deltas
    float ld0 = hw0 * invS0 - (float)(SEG - c0) * invd0;
    float ld1 = hw1 * invS1 - (float)(SEG - c1) * invd1;
    float v0 = ld0, v1 = ld1;
    #pragma unroll
    for (int off = 1; off < 32; off <<= 1) {
        float n0 = __shfl_up_sync(0xffffffffu, v0, off);
        float n1 = __shfl_up_sync(0xffffffffu, v1, off);
        if (lane >= off) { v0 += n0; v1 += n1; }
    }
    float r0 = v0 - ld0;
    float r1 = v1 - ld1;

    // pass B: serial running sums, track first argmax |r|
    float ba0 = -1.0f, bv0 = 0.0f;  int bi0 = 0x7fffffff;
    float ba1 = -1.0f, bv1 = 0.0f;  int bi1 = 0x7fffffff;
    {
        unsigned m0 = 0, m1 = 0;
        for (int k = 0; k < SEG; k++) {
            int i  = start + k;
            int sh = i & 31;
            if (k == 0 || sh == 0) { m0 = mp0[i >> 5]; m1 = mp1[i >> 5]; }
            float wv = s_w[i];
            r0 = ((m0 >> sh) & 1u) ? fmaf(wv, invS0, r0) : (r0 - invd0);
            r1 = ((m1 >> sh) & 1u) ? fmaf(wv, invS1, r1) : (r1 - invd1);
            float a0 = fabsf(r0), a1 = fabsf(r1);
            if (a0 > ba0) { ba0 = a0; bv0 = r0; bi0 = i; }
            if (a1 > ba1) { ba1 = a1; bv1 = r1; bi1 = i; }
        }
    }

    // cross-lane argmax reduce (tie -> smallest index)
    #pragma unroll
    for (int off = 16; off; off >>= 1) {
        float oa0 = __shfl_down_sync(0xffffffffu, ba0, off);
        float ov0 = __shfl_down_sync(0xffffffffu, bv0, off);
        int   oi0 = __shfl_down_sync(0xffffffffu, bi0, off);
        float oa1 = __shfl_down_sync(0xffffffffu, ba1, off);
        float ov1 = __shfl_down_sync(0xffffffffu, bv1, off);
        int   oi1 = __shfl_down_sync(0xffffffffu, bi1, off);
        if (oa0 > ba0 || (oa0 == ba0 && oi0 < bi0)) { ba0 = oa0; bv0 = ov0; bi0 = oi0; }
        if (oa1 > ba1 || (oa1 == ba1 && oi1 < bi1)) { ba1 = oa1; bv1 = ov1; bi1 = oi1; }
    }
    if (lane == 0) {
        out[b * PN + p0]     = (size0 > 0) ? bv0 : 0.0f;
        out[b * PN + p0 + 1] = (size1 > 0) ? bv1 : 0.0f;
    }
}

// ---------------------------------------------------------------------------
extern "C" void kernel_launch(void* const* d_in, const int* in_sizes, int n_in,
                              void* d_out, int out_size) {
    const float* expr = (const float*)d_in[0];   // [B, G]
    const float* pw   = (const float*)d_in[1];   // [P, G]
    float* out        = (float*)d_out;           // [B, P]

    cudaFuncSetAttribute(fused_kernel,
                         cudaFuncAttributeMaxDynamicSharedMemorySize, SMEM_TOTAL);

    pbuild_kernel<<<(GN + 127) / 128, 128>>>(pw);
    fused_kernel<<<BN, ST, SMEM_TOTAL>>>(expr, out);
}